// round 14
// baseline (speedup 1.0000x reference)
#include <cuda_runtime.h>
#include <cuda_fp16.h>
#include <cstdint>

#define D_DIM     1024
#define DFF       4096
#define NE        8
#define T_MAX     4096
#define BM        128
#define BN        128
#define KC        64
#define NSTAGE    3
#define MAX_TILES 72
#define ROWB      144                   // 128B data (64 fp16) + 16B pad, conflict-free
#define OFF_B     (128 * ROWB)          // 18432
#define STAGEB    (OFF_B + 128 * ROWB)  // 36864
#define SMEM_DYN  (NSTAGE * STAGEB)     // 110592 per CTA (2 CTAs/SM = 221184)

// ---------------- device scratch (NEVER passed as kernel args) ----------------
__device__ int   g_cnt[NE];
__device__ int   g_bucket[NE * T_MAX];
__device__ int2  g_pos[T_MAX];
__device__ int   g_tile_e[MAX_TILES];
__device__ int   g_tile_m0[MAX_TILES];
__device__ int   g_ebase[NE];

__device__ __half g_A[(size_t)MAX_TILES * BM * D_DIM];
__device__ __half g_W1t[(size_t)NE * DFF * D_DIM];
__device__ __half g_W2t[(size_t)NE * D_DIM * DFF];
__device__ __half g_H[(size_t)MAX_TILES * BM * DFF];
__device__ float  g_part[(size_t)MAX_TILES * BM * D_DIM];

// ---------------- helpers ----------------
__device__ __forceinline__ uint32_t smem_u32(const void* p) {
    uint32_t a;
    asm("{ .reg .u64 t; cvta.to.shared.u64 t, %1; cvt.u32.u64 %0, t; }" : "=r"(a) : "l"(p));
    return a;
}
__device__ __forceinline__ uint32_t pack_h2(float a, float b) {
    __half2 t = __floats2half2_rn(a, b);
    return *reinterpret_cast<uint32_t*>(&t);
}
__device__ __forceinline__ void cp16(uint32_t dst, const void* src) {
    asm volatile("cp.async.cg.shared.global [%0], [%1], 16;" :: "r"(dst), "l"(src));
}
__device__ __forceinline__ void cp_commit() {
    asm volatile("cp.async.commit_group;" ::: "memory");
}
__device__ __forceinline__ void ldm_x4(uint32_t* r, uint32_t addr) {
    asm volatile("ldmatrix.sync.aligned.m8n8.x4.shared.b16 {%0,%1,%2,%3}, [%4];"
                 : "=r"(r[0]), "=r"(r[1]), "=r"(r[2]), "=r"(r[3]) : "r"(addr));
}
__device__ __forceinline__ void mma_f16(float* c, const uint32_t* a,
                                        uint32_t b0, uint32_t b1) {
    asm volatile("mma.sync.aligned.m16n8k16.row.col.f32.f16.f16.f32 "
                 "{%0,%1,%2,%3}, {%4,%5,%6,%7}, {%8,%9}, {%0,%1,%2,%3};"
                 : "+f"(c[0]), "+f"(c[1]), "+f"(c[2]), "+f"(c[3])
                 : "r"(a[0]), "r"(a[1]), "r"(a[2]), "r"(a[3]), "r"(b0), "r"(b1));
}
__device__ __forceinline__ int route_h(const float* x, int t) {
    float s = x[(size_t)t * D_DIM] + x[(size_t)t * D_DIM + 1];
    int i = (int)s;
    return ((i % NE) + NE) % NE;
}

// ---------------- routing ----------------
__global__ void zero_cnt_kernel() { if (threadIdx.x < NE) g_cnt[threadIdx.x] = 0; }

__global__ void route_kernel(const float* __restrict__ x, int T) {
    int t = blockIdx.x * blockDim.x + threadIdx.x;
    if (t >= T) return;
    int h = route_h(x, t);
    int e0 = h, e1 = (h + 1) & (NE - 1);
    int p0 = atomicAdd(&g_cnt[e0], 1);
    g_bucket[e0 * T_MAX + p0] = t;
    int p1 = atomicAdd(&g_cnt[e1], 1);
    g_bucket[e1 * T_MAX + p1] = t;
    g_pos[t] = make_int2(p0, p1);
}

__global__ void tilemap_kernel() {
    if (threadIdx.x != 0) return;
    int tt = 0;
    for (int e = 0; e < NE; e++) {
        g_ebase[e] = tt * BM;
        int nt = (g_cnt[e] + BM - 1) / BM;
        for (int i = 0; i < nt && tt < MAX_TILES; i++) {
            g_tile_e[tt] = e; g_tile_m0[tt] = i * BM; tt++;
        }
    }
    for (; tt < MAX_TILES; tt++) g_tile_e[tt] = -1;
}

// ---------------- gather + convert A -> fp16 ----------------
__global__ __launch_bounds__(256)
void convertA_kernel(const float* __restrict__ x) {
    int tt = blockIdx.x;
    int e = g_tile_e[tt];
    if (e < 0) return;
    int m0 = g_tile_m0[tt], cnt = g_cnt[e];
    int sub = blockIdx.y;                      // 8 sub-blocks of 16 rows
    for (int idx = threadIdx.x; idx < 16 * 256; idx += 256) {
        int r = sub * 16 + (idx >> 8);
        int c4 = (idx & 255) * 4;
        int m = m0 + r;
        int tok = (m < cnt) ? g_bucket[e * T_MAX + m] : -1;
        float4 v = make_float4(0.f, 0.f, 0.f, 0.f);
        if (tok >= 0) v = *(const float4*)(x + (size_t)tok * D_DIM + c4);
        uint2 hp;
        hp.x = pack_h2(v.x, v.y); hp.y = pack_h2(v.z, v.w);
        *(uint2*)(g_A + ((size_t)tt * BM + r) * D_DIM + c4) = hp;
    }
}

// ---- transpose + convert W: [E][K][N] f32 -> [E][N][K] fp16 ----
template<int WHICH>
__global__ __launch_bounds__(256)
void convertW_kernel(const float* __restrict__ W) {
    constexpr int K = (WHICH == 1) ? D_DIM : DFF;
    constexpr int N = (WHICH == 1) ? DFF : D_DIM;
    __half* Dh = (WHICH == 1) ? g_W1t : g_W2t;

    __shared__ float ts[64][33];
    int e = blockIdx.z;
    const float* We = W + (size_t)e * K * N;
    int nb = blockIdx.x * 32, kb = blockIdx.y * 64;
    int tx = threadIdx.x, ty = threadIdx.y;
    #pragma unroll
    for (int i = 0; i < 8; i++) {
        int kl = ty + i * 8;
        ts[kl][tx] = We[(size_t)(kb + kl) * N + nb + tx];
    }
    __syncthreads();
    #pragma unroll
    for (int i = 0; i < 4; i++) {
        int nl = ty + i * 8;
        float v0 = ts[2 * tx][nl], v1 = ts[2 * tx + 1][nl];
        size_t off = ((size_t)e * N + nb + nl) * K + kb + 2 * tx;
        *(uint32_t*)(Dh + off) = pack_h2(v0, v1);
    }
}

// ---------------- fp16 HMMA grouped GEMM (single pass) ----------------
// 256 threads, CTA tile 128x128, KC=64, 3-stage cp.async (wait_group 1), 2 CTAs/SM.
// Grid: x = n-tile (fast), y = tile  -- measured-optimal orientation.
// MODE 1: H = relu(x@W1 + b1) -> fp16.   MODE 2: part = H@W2 (fp32).
template<int KT, int MODE, int NTOT>
__global__ __launch_bounds__(256, 2)
void moe_gemm_hmma(const float* __restrict__ bias) {
    extern __shared__ __align__(128) char smem[];

    int tt = blockIdx.y;
    int e = g_tile_e[tt];
    if (e < 0) return;
    int n0 = blockIdx.x * BN;

    uint32_t sb = smem_u32(smem);
    int tid = threadIdx.x, lane = tid & 31, wid = tid >> 5;
    int wm0 = (wid & 1) * 64;          // 2 warps along M
    int wn0 = (wid >> 1) * 32;         // 4 warps along N

    const __half *A, *B;
    if (MODE == 1) { A = g_A; B = g_W1t; }
    else           { A = g_H; B = g_W2t; }
    A += (size_t)tt * BM * KT;
    B += ((size_t)e * NTOT + n0) * KT;

    // per-lane ldmatrix geometry (padded rows, conflict-free: 144*r8 % 128 = 16*r8)
    int m4 = lane >> 3;
    int r8 = lane & 7;
    int aHalf = (m4 >> 1) * 16;
    int aRowLoc = (m4 & 1) * 8 + r8;
    int bHalf = (m4 & 1) * 16;
    int bRowLoc = (m4 >> 1) * 8 + r8;

    uint32_t aCore[4], bCore[2];
    #pragma unroll
    for (int mi = 0; mi < 4; mi++)
        aCore[mi] = (uint32_t)((wm0 + 16 * mi + aRowLoc) * ROWB + aHalf);
    #pragma unroll
    for (int p = 0; p < 2; p++)
        bCore[p]  = (uint32_t)((wn0 + 16 * p + bRowLoc) * ROWB + bHalf);

    // loader: 8 x 16B cp.async per thread per chunk
    const __half* lsrc[8];
    uint32_t ldst[8];
    #pragma unroll
    for (int i = 0; i < 8; i++) {
        int idx = tid + i * 256;       // 0..2047
        const __half* base;
        uint32_t soff;
        int sub = idx & 1023;
        int row = sub >> 3, c16 = sub & 7;
        if (idx < 1024) { base = A; soff = 0; }
        else            { base = B; soff = OFF_B; }
        lsrc[i] = base + (size_t)row * KT + c16 * 8;
        ldst[i] = soff + (uint32_t)(row * ROWB + c16 * 16);
    }

    float acc[4][4][4];
    #pragma unroll
    for (int i = 0; i < 4; i++)
        #pragma unroll
        for (int j = 0; j < 4; j++)
            #pragma unroll
            for (int q = 0; q < 4; q++) acc[i][j][q] = 0.f;

    const int NC = KT / KC;            // 16 or 64 (>= NSTAGE)

    // prologue: stages 0..NSTAGE-2
    #pragma unroll
    for (int s = 0; s < NSTAGE - 1; s++) {
        uint32_t st = sb + s * STAGEB;
        int k0 = s * KC;
        #pragma unroll
        for (int i = 0; i < 8; i++) cp16(st + ldst[i], lsrc[i] + k0);
        cp_commit();
    }

    for (int c = 0; c < NC; c++) {
        // pending: {c, c+1}; wait_group 1 -> group c complete
        asm volatile("cp.async.wait_group %0;" :: "n"(NSTAGE - 2) : "memory");
        __syncthreads();

        // prefetch chunk c+2 into stage (c+2)%3 (freed: compute(c-1) done pre-barrier)
        if (c + NSTAGE - 1 < NC) {
            uint32_t st = sb + ((c + NSTAGE - 1) % NSTAGE) * STAGEB;
            int k0 = (c + NSTAGE - 1) * KC;
            #pragma unroll
            for (int i = 0; i < 8; i++) cp16(st + ldst[i], lsrc[i] + k0);
        }
        cp_commit();   // always commit (possibly empty) to keep pending invariant

        uint32_t cs = sb + (c % NSTAGE) * STAGEB;
        uint32_t sA = cs, sB = cs + OFF_B;

        #pragma unroll
        for (int kk = 0; kk < 4; kk++) {
            uint32_t ko = (uint32_t)(kk * 32);
            uint32_t ah[4][4];
            #pragma unroll
            for (int mi = 0; mi < 4; mi++) ldm_x4(ah[mi], sA + aCore[mi] + ko);
            #pragma unroll
            for (int p = 0; p < 2; p++) {
                uint32_t rb[4];
                ldm_x4(rb, sB + bCore[p] + ko);
                #pragma unroll
                for (int mi = 0; mi < 4; mi++) {
                    mma_f16(acc[mi][2 * p],     ah[mi], rb[0], rb[1]);
                    mma_f16(acc[mi][2 * p + 1], ah[mi], rb[2], rb[3]);
                }
            }
        }
    }

    // ---------------- epilogue ----------------
    int trow = lane >> 2;
    int tcol = (lane & 3) * 2;
    #pragma unroll
    for (int ni = 0; ni < 4; ni++) {
        int col = wn0 + 8 * ni + tcol;
        float b0 = 0.f, b1 = 0.f;
        if (MODE == 1) {
            b0 = __ldg(bias + (size_t)e * DFF + n0 + col);
            b1 = __ldg(bias + (size_t)e * DFF + n0 + col + 1);
        }
        #pragma unroll
        for (int mi = 0; mi < 4; mi++) {
            float* cc = acc[mi][ni];
            #pragma unroll
            for (int half = 0; half < 2; half++) {
                int row = wm0 + 16 * mi + trow + half * 8;
                size_t slot = (size_t)tt * BM + row;
                float v0 = cc[2 * half], v1 = cc[2 * half + 1];
                if (MODE == 1) {
                    v0 = fmaxf(v0 + b0, 0.f);
                    v1 = fmaxf(v1 + b1, 0.f);
                    *(uint32_t*)(g_H + slot * DFF + n0 + col) = pack_h2(v0, v1);
                } else {
                    *(float2*)(g_part + slot * D_DIM + n0 + col) = make_float2(v0, v1);
                }
            }
        }
    }
}

// ---------------- combine: out = 0.5*(p0 + p1 + b2[e0] + b2[e1]) ----------------
__global__ __launch_bounds__(256)
void combine_kernel(const float* __restrict__ x, const float* __restrict__ b2,
                    float* __restrict__ out) {
    int t = blockIdx.x;
    int h = route_h(x, t);
    int e0 = h, e1 = (h + 1) & (NE - 1);
    int2 pp = g_pos[t];
    const float* p0 = g_part + (size_t)(g_ebase[e0] + pp.x) * D_DIM;
    const float* p1 = g_part + (size_t)(g_ebase[e1] + pp.y) * D_DIM;
    const float* ba = b2 + (size_t)e0 * D_DIM;
    const float* bb = b2 + (size_t)e1 * D_DIM;
    int c = threadIdx.x * 4;
    float4 a = *(const float4*)(p0 + c);
    float4 b = *(const float4*)(p1 + c);
    float4 va = *(const float4*)(ba + c);
    float4 vb = *(const float4*)(bb + c);
    float4 o;
    o.x = 0.5f * (a.x + b.x + va.x + vb.x);
    o.y = 0.5f * (a.y + b.y + va.y + vb.y);
    o.z = 0.5f * (a.z + b.z + va.z + vb.z);
    o.w = 0.5f * (a.w + b.w + va.w + vb.w);
    *(float4*)(out + (size_t)t * D_DIM + c) = o;
}

// ---------------- launch ----------------
extern "C" void kernel_launch(void* const* d_in, const int* in_sizes, int n_in,
                              void* d_out, int out_size) {
    const float* x  = (const float*)d_in[0];
    const float* W1 = (const float*)d_in[1];
    const float* b1 = (const float*)d_in[2];
    const float* W2 = (const float*)d_in[3];
    const float* b2 = (const float*)d_in[4];
    float* out = (float*)d_out;

    int T = in_sizes[0] / D_DIM;
    if (T > T_MAX) T = T_MAX;

    cudaFuncSetAttribute(moe_gemm_hmma<D_DIM, 1, DFF>,
                         cudaFuncAttributeMaxDynamicSharedMemorySize, SMEM_DYN);
    cudaFuncSetAttribute(moe_gemm_hmma<DFF, 2, D_DIM>,
                         cudaFuncAttributeMaxDynamicSharedMemorySize, SMEM_DYN);

    zero_cnt_kernel<<<1, 32>>>();
    route_kernel<<<(T + 255) / 256, 256>>>(x, T);
    tilemap_kernel<<<1, 32>>>();
    convertA_kernel<<<dim3(MAX_TILES, 8), 256>>>(x);
    convertW_kernel<1><<<dim3(DFF / 32, D_DIM / 64, NE), dim3(32, 8)>>>(W1);
    convertW_kernel<2><<<dim3(D_DIM / 32, DFF / 64, NE), dim3(32, 8)>>>(W2);
    moe_gemm_hmma<D_DIM, 1, DFF><<<dim3(DFF / BN, MAX_TILES), 256, SMEM_DYN>>>(b1);
    moe_gemm_hmma<DFF, 2, D_DIM><<<dim3(D_DIM / BN, MAX_TILES), 256, SMEM_DYN>>>(b1);
    combine_kernel<<<T, 256>>>(x, b2, out);
}

// round 15
// speedup vs baseline: 1.0191x; 1.0191x over previous
#include <cuda_runtime.h>
#include <cuda_fp16.h>
#include <cstdint>

#define D_DIM     1024
#define DFF       4096
#define NE        8
#define T_MAX     4096
#define BM        128
#define BN        128
#define KC        64
#define NSTAGE    2
#define MAX_TILES 72
#define ROWB      144                   // 128B data (64 fp16) + 16B pad, conflict-free
#define OFF_B     (128 * ROWB)          // 18432
#define STAGEB    (OFF_B + 128 * ROWB)  // 36864
#define SMEM_DYN  (NSTAGE * STAGEB)     // 73728 per CTA (2 CTAs/SM)

// ---------------- device scratch (NEVER passed as kernel args) ----------------
__device__ int   g_cnt[NE];
__device__ int   g_bucket[NE * T_MAX];
__device__ int2  g_pos[T_MAX];
__device__ int   g_tile_e[MAX_TILES];
__device__ int   g_tile_m0[MAX_TILES];
__device__ int   g_ebase[NE];

__device__ __half g_A[(size_t)MAX_TILES * BM * D_DIM];
__device__ __half g_W1t[(size_t)NE * DFF * D_DIM];
__device__ __half g_W2t[(size_t)NE * D_DIM * DFF];
__device__ __half g_H[(size_t)MAX_TILES * BM * DFF];
__device__ float  g_part[(size_t)MAX_TILES * BM * D_DIM];

// ---------------- helpers ----------------
__device__ __forceinline__ uint32_t smem_u32(const void* p) {
    uint32_t a;
    asm("{ .reg .u64 t; cvta.to.shared.u64 t, %1; cvt.u32.u64 %0, t; }" : "=r"(a) : "l"(p));
    return a;
}
__device__ __forceinline__ uint32_t pack_h2(float a, float b) {
    __half2 t = __floats2half2_rn(a, b);
    return *reinterpret_cast<uint32_t*>(&t);
}
__device__ __forceinline__ void cp16(uint32_t dst, const void* src) {
    asm volatile("cp.async.cg.shared.global [%0], [%1], 16;" :: "r"(dst), "l"(src));
}
__device__ __forceinline__ void cp_commit() {
    asm volatile("cp.async.commit_group;" ::: "memory");
}
__device__ __forceinline__ void ldm_x4(uint32_t* r, uint32_t addr) {
    asm volatile("ldmatrix.sync.aligned.m8n8.x4.shared.b16 {%0,%1,%2,%3}, [%4];"
                 : "=r"(r[0]), "=r"(r[1]), "=r"(r[2]), "=r"(r[3]) : "r"(addr));
}
__device__ __forceinline__ void mma_f16(float* c, const uint32_t* a,
                                        uint32_t b0, uint32_t b1) {
    asm volatile("mma.sync.aligned.m16n8k16.row.col.f32.f16.f16.f32 "
                 "{%0,%1,%2,%3}, {%4,%5,%6,%7}, {%8,%9}, {%0,%1,%2,%3};"
                 : "+f"(c[0]), "+f"(c[1]), "+f"(c[2]), "+f"(c[3])
                 : "r"(a[0]), "r"(a[1]), "r"(a[2]), "r"(a[3]), "r"(b0), "r"(b1));
}
__device__ __forceinline__ int route_h(const float* x, int t) {
    float s = x[(size_t)t * D_DIM] + x[(size_t)t * D_DIM + 1];
    int i = (int)s;
    return ((i % NE) + NE) % NE;
}

// ---------------- fused routing: zero + route + tilemap, single CTA ----------------
__global__ __launch_bounds__(1024)
void route_fused_kernel(const float* __restrict__ x, int T) {
    __shared__ int scnt[NE];
    int tid = threadIdx.x;
    if (tid < NE) scnt[tid] = 0;
    __syncthreads();
    for (int t = tid; t < T; t += 1024) {
        int h = route_h(x, t);
        int e0 = h, e1 = (h + 1) & (NE - 1);
        int p0 = atomicAdd(&scnt[e0], 1);
        g_bucket[e0 * T_MAX + p0] = t;
        int p1 = atomicAdd(&scnt[e1], 1);
        g_bucket[e1 * T_MAX + p1] = t;
        g_pos[t] = make_int2(p0, p1);
    }
    __syncthreads();
    if (tid == 0) {
        int tt = 0;
        for (int e = 0; e < NE; e++) {
            int c = scnt[e];
            g_cnt[e] = c;
            g_ebase[e] = tt * BM;
            int nt = (c + BM - 1) / BM;
            for (int i = 0; i < nt && tt < MAX_TILES; i++) {
                g_tile_e[tt] = e; g_tile_m0[tt] = i * BM; tt++;
            }
        }
        for (; tt < MAX_TILES; tt++) g_tile_e[tt] = -1;
    }
}

// ---------------- gather + convert A -> fp16 ----------------
__global__ __launch_bounds__(256)
void convertA_kernel(const float* __restrict__ x) {
    int tt = blockIdx.x;
    int e = g_tile_e[tt];
    if (e < 0) return;
    int m0 = g_tile_m0[tt], cnt = g_cnt[e];
    int sub = blockIdx.y;                      // 8 sub-blocks of 16 rows
    for (int idx = threadIdx.x; idx < 16 * 256; idx += 256) {
        int r = sub * 16 + (idx >> 8);
        int c4 = (idx & 255) * 4;
        int m = m0 + r;
        int tok = (m < cnt) ? g_bucket[e * T_MAX + m] : -1;
        float4 v = make_float4(0.f, 0.f, 0.f, 0.f);
        if (tok >= 0) v = *(const float4*)(x + (size_t)tok * D_DIM + c4);
        uint2 hp;
        hp.x = pack_h2(v.x, v.y); hp.y = pack_h2(v.z, v.w);
        *(uint2*)(g_A + ((size_t)tt * BM + r) * D_DIM + c4) = hp;
    }
}

// ---- unified transpose + convert W: [E][K][N] f32 -> [E][N][K] fp16 ----
// grid: (2048, NE, 2); z selects W1 vs W2.
__global__ __launch_bounds__(256)
void convertW_kernel(const float* __restrict__ W1src, const float* __restrict__ W2src) {
    int which = blockIdx.z;
    int K = which ? DFF : D_DIM;
    int N = which ? D_DIM : DFF;
    const float* W = which ? W2src : W1src;
    __half* Dh = which ? g_W2t : g_W1t;

    int bx = blockIdx.x;
    int nbIdx, kbIdx;
    if (which) { nbIdx = bx & 31;  kbIdx = bx >> 5; }   // N/32=32, K/64=64
    else       { nbIdx = bx & 127; kbIdx = bx >> 7; }   // N/32=128, K/64=16

    __shared__ float ts[64][33];
    int e = blockIdx.y;
    const float* We = W + (size_t)e * K * N;
    int nb = nbIdx * 32, kb = kbIdx * 64;
    int tx = threadIdx.x & 31, ty = threadIdx.x >> 5;
    #pragma unroll
    for (int i = 0; i < 8; i++) {
        int kl = ty + i * 8;
        ts[kl][tx] = We[(size_t)(kb + kl) * N + nb + tx];
    }
    __syncthreads();
    #pragma unroll
    for (int i = 0; i < 4; i++) {
        int nl = ty + i * 8;
        float v0 = ts[2 * tx][nl], v1 = ts[2 * tx + 1][nl];
        size_t off = ((size_t)e * N + nb + nl) * K + kb + 2 * tx;
        *(uint32_t*)(Dh + off) = pack_h2(v0, v1);
    }
}

// ---------------- fp16 HMMA grouped GEMM (single pass) ----------------
// 256 threads, CTA tile 128x128, KC=64, 2-stage cp.async, 2 CTAs/SM.
// Grid: x = n-tile (fast), y = tile  -- measured-optimal orientation.
// MODE 1: H = relu(x@W1 + b1) -> fp16.   MODE 2: part = H@W2 (fp32).
template<int KT, int MODE, int NTOT>
__global__ __launch_bounds__(256, 2)
void moe_gemm_hmma(const float* __restrict__ bias) {
    extern __shared__ __align__(128) char smem[];

    int tt = blockIdx.y;
    int e = g_tile_e[tt];
    if (e < 0) return;
    int n0 = blockIdx.x * BN;

    uint32_t sb = smem_u32(smem);
    int tid = threadIdx.x, lane = tid & 31, wid = tid >> 5;
    int wm0 = (wid & 1) * 64;          // 2 warps along M
    int wn0 = (wid >> 1) * 32;         // 4 warps along N

    const __half *A, *B;
    if (MODE == 1) { A = g_A; B = g_W1t; }
    else           { A = g_H; B = g_W2t; }
    A += (size_t)tt * BM * KT;
    B += ((size_t)e * NTOT + n0) * KT;

    // per-lane ldmatrix geometry (padded rows, conflict-free: 144*r8 % 128 = 16*r8)
    int m4 = lane >> 3;
    int r8 = lane & 7;
    int aHalf = (m4 >> 1) * 16;
    int aRowLoc = (m4 & 1) * 8 + r8;
    int bHalf = (m4 & 1) * 16;
    int bRowLoc = (m4 >> 1) * 8 + r8;

    uint32_t aCore[4], bCore[2];
    #pragma unroll
    for (int mi = 0; mi < 4; mi++)
        aCore[mi] = (uint32_t)((wm0 + 16 * mi + aRowLoc) * ROWB + aHalf);
    #pragma unroll
    for (int p = 0; p < 2; p++)
        bCore[p]  = (uint32_t)((wn0 + 16 * p + bRowLoc) * ROWB + bHalf);

    // loader: 8 x 16B cp.async per thread per chunk
    const __half* lsrc[8];
    uint32_t ldst[8];
    #pragma unroll
    for (int i = 0; i < 8; i++) {
        int idx = tid + i * 256;       // 0..2047
        const __half* base;
        uint32_t soff;
        int sub = idx & 1023;
        int row = sub >> 3, c16 = sub & 7;
        if (idx < 1024) { base = A; soff = 0; }
        else            { base = B; soff = OFF_B; }
        lsrc[i] = base + (size_t)row * KT + c16 * 8;
        ldst[i] = soff + (uint32_t)(row * ROWB + c16 * 16);
    }

    float acc[4][4][4];
    #pragma unroll
    for (int i = 0; i < 4; i++)
        #pragma unroll
        for (int j = 0; j < 4; j++)
            #pragma unroll
            for (int q = 0; q < 4; q++) acc[i][j][q] = 0.f;

    const int NC = KT / KC;            // 16 or 64

    // prologue: stage 0
    #pragma unroll
    for (int i = 0; i < 8; i++) cp16(sb + ldst[i], lsrc[i]);
    cp_commit();

    for (int c = 0; c < NC; c++) {
        asm volatile("cp.async.wait_group 0;" ::: "memory");
        __syncthreads();

        if (c + 1 < NC) {
            uint32_t st = sb + ((c + 1) & 1) * STAGEB;
            int k0 = (c + 1) * KC;
            #pragma unroll
            for (int i = 0; i < 8; i++) cp16(st + ldst[i], lsrc[i] + k0);
            cp_commit();
        }

        uint32_t cs = sb + (c & 1) * STAGEB;
        uint32_t sA = cs, sB = cs + OFF_B;

        #pragma unroll
        for (int kk = 0; kk < 4; kk++) {
            uint32_t ko = (uint32_t)(kk * 32);
            uint32_t ah[4][4];
            #pragma unroll
            for (int mi = 0; mi < 4; mi++) ldm_x4(ah[mi], sA + aCore[mi] + ko);
            #pragma unroll
            for (int p = 0; p < 2; p++) {
                uint32_t rb[4];
                ldm_x4(rb, sB + bCore[p] + ko);
                #pragma unroll
                for (int mi = 0; mi < 4; mi++) {
                    mma_f16(acc[mi][2 * p],     ah[mi], rb[0], rb[1]);
                    mma_f16(acc[mi][2 * p + 1], ah[mi], rb[2], rb[3]);
                }
            }
        }
    }

    // ---------------- epilogue ----------------
    int trow = lane >> 2;
    int tcol = (lane & 3) * 2;
    #pragma unroll
    for (int ni = 0; ni < 4; ni++) {
        int col = wn0 + 8 * ni + tcol;
        float b0 = 0.f, b1 = 0.f;
        if (MODE == 1) {
            b0 = __ldg(bias + (size_t)e * DFF + n0 + col);
            b1 = __ldg(bias + (size_t)e * DFF + n0 + col + 1);
        }
        #pragma unroll
        for (int mi = 0; mi < 4; mi++) {
            float* cc = acc[mi][ni];
            #pragma unroll
            for (int half = 0; half < 2; half++) {
                int row = wm0 + 16 * mi + trow + half * 8;
                size_t slot = (size_t)tt * BM + row;
                float v0 = cc[2 * half], v1 = cc[2 * half + 1];
                if (MODE == 1) {
                    v0 = fmaxf(v0 + b0, 0.f);
                    v1 = fmaxf(v1 + b1, 0.f);
                    *(uint32_t*)(g_H + slot * DFF + n0 + col) = pack_h2(v0, v1);
                } else {
                    *(float2*)(g_part + slot * D_DIM + n0 + col) = make_float2(v0, v1);
                }
            }
        }
    }
}

// ---------------- combine: out = 0.5*(p0 + p1 + b2[e0] + b2[e1]) ----------------
__global__ __launch_bounds__(256)
void combine_kernel(const float* __restrict__ x, const float* __restrict__ b2,
                    float* __restrict__ out) {
    int t = blockIdx.x;
    int h = route_h(x, t);
    int e0 = h, e1 = (h + 1) & (NE - 1);
    int2 pp = g_pos[t];
    const float* p0 = g_part + (size_t)(g_ebase[e0] + pp.x) * D_DIM;
    const float* p1 = g_part + (size_t)(g_ebase[e1] + pp.y) * D_DIM;
    const float* ba = b2 + (size_t)e0 * D_DIM;
    const float* bb = b2 + (size_t)e1 * D_DIM;
    int c = threadIdx.x * 4;
    float4 a = *(const float4*)(p0 + c);
    float4 b = *(const float4*)(p1 + c);
    float4 va = *(const float4*)(ba + c);
    float4 vb = *(const float4*)(bb + c);
    float4 o;
    o.x = 0.5f * (a.x + b.x + va.x + vb.x);
    o.y = 0.5f * (a.y + b.y + va.y + vb.y);
    o.z = 0.5f * (a.z + b.z + va.z + vb.z);
    o.w = 0.5f * (a.w + b.w + va.w + vb.w);
    *(float4*)(out + (size_t)t * D_DIM + c) = o;
}

// ---------------- launch ----------------
extern "C" void kernel_launch(void* const* d_in, const int* in_sizes, int n_in,
                              void* d_out, int out_size) {
    const float* x  = (const float*)d_in[0];
    const float* W1 = (const float*)d_in[1];
    const float* b1 = (const float*)d_in[2];
    const float* W2 = (const float*)d_in[3];
    const float* b2 = (const float*)d_in[4];
    float* out = (float*)d_out;

    int T = in_sizes[0] / D_DIM;
    if (T > T_MAX) T = T_MAX;

    cudaFuncSetAttribute(moe_gemm_hmma<D_DIM, 1, DFF>,
                         cudaFuncAttributeMaxDynamicSharedMemorySize, SMEM_DYN);
    cudaFuncSetAttribute(moe_gemm_hmma<DFF, 2, D_DIM>,
                         cudaFuncAttributeMaxDynamicSharedMemorySize, SMEM_DYN);

    route_fused_kernel<<<1, 1024>>>(x, T);
    convertA_kernel<<<dim3(MAX_TILES, 8), 256>>>(x);
    convertW_kernel<<<dim3(2048, NE, 2), 256>>>(W1, W2);
    moe_gemm_hmma<D_DIM, 1, DFF><<<dim3(DFF / BN, MAX_TILES), 256, SMEM_DYN>>>(b1);
    moe_gemm_hmma<DFF, 2, D_DIM><<<dim3(D_DIM / BN, MAX_TILES), 256, SMEM_DYN>>>(b1);
    combine_kernel<<<T, 256>>>(x, b2, out);
}